// round 16
// baseline (speedup 1.0000x reference)
#include <cuda_runtime.h>
#include <cuda_fp16.h>
#include <math.h>

#define NUM_USERS 60000
#define NUM_ITEMS 40000
#define NUM_NODES 100000
#define EMB 64
#define HID 32
#define N_EDGES 1600000
#define BATCH 16384

#define SCAN_BLK 1024
#define NB ((NUM_NODES + SCAN_BLK - 1) / SCAN_BLK)   // 98

#define ST_AGG  (1 << 30)
#define ST_INCL (2 << 30)
#define ST_VAL  0x3FFFFFFF

#define HIST_BLOCKS 148

// ---------------- device scratch (allocation-free rule) ----------------
__device__ __align__(16) __half g_h1h[NUM_NODES * HID];   // lin1 out, fp16 (64B/row)
__device__ __align__(16) __half g_yh[NUM_NODES * HID];    // relu(agg1), fp16 (64B/row)
__device__ __align__(16) float  g_agg[NUM_NODES * HID];   // layer-2 agg, row-major [node][k]
__device__ float g_s[NUM_NODES];                          // per-row sum of vals
__device__ int   g_counts[NUM_NODES];                     // degree hist / cursor (zeroed by predict tail)
__device__ int   g_row_ptr[NUM_NODES + 1];
__device__ int   g_tile_state[NB];                        // lookback states (zeroed by predict tail)
__device__ __align__(8) int2 g_epk[N_EDGES];              // (col, half2(v,v) bits), CSR order

// ---------------------------------------------------------------------------
// Fused lin1 + degree histogram. Blocks [0,HIST_BLOCKS) histogram; rest lin1.
__global__ void lin1_hist_kernel(const float* __restrict__ uemb,
                                 const float* __restrict__ iemb,
                                 const float* __restrict__ W,
                                 const float* __restrict__ b,
                                 const int* __restrict__ rows) {
    int lane = threadIdx.x & 31;

    if (blockIdx.x < HIST_BLOCKS) {
        int t = blockIdx.x * blockDim.x + threadIdx.x;
        int nthr = HIST_BLOCKS * blockDim.x;
        for (int e4 = t * 4; e4 < N_EDGES; e4 += nthr * 4) {
            int4 r4 = *(const int4*)(rows + e4);      // N_EDGES % 4 == 0
            atomicAdd(&g_counts[r4.x], 1);
            atomicAdd(&g_counts[r4.y], 1);
            atomicAdd(&g_counts[r4.z], 1);
            atomicAdd(&g_counts[r4.w], 1);
        }
        return;
    }

    __shared__ float sW[EMB][HID + 1];   // sW[k][j] = W1[j][k]
    int tid = threadIdx.x;
    for (int i = tid; i < HID * EMB; i += blockDim.x) {
        int j = i >> 6, k = i & 63;
        sW[k][j] = W[i];
    }
    __syncthreads();

    float w[EMB];
#pragma unroll
    for (int k = 0; k < EMB; k++) w[k] = sW[k][lane];   // conflict-free
    float bias = __ldg(&b[lane]);

    int wl = (blockIdx.x - HIST_BLOCKS) * (blockDim.x >> 5) + (tid >> 5);
    int nl = (gridDim.x - HIST_BLOCKS) * (blockDim.x >> 5);

    for (int node = wl; node < NUM_NODES; node += nl) {
        const float* feat = (node < NUM_USERS)
            ? uemb + (size_t)node * EMB
            : iemb + (size_t)(node - NUM_USERS) * EMB;
        float x0 = __ldg(&feat[lane]);
        float x1 = __ldg(&feat[lane + 32]);
        float acc = bias;
#pragma unroll
        for (int k = 0; k < 32; k++) {
            acc += __shfl_sync(0xffffffffu, x0, k) * w[k];
            acc += __shfl_sync(0xffffffffu, x1, k) * w[k + 32];
        }
        g_h1h[(size_t)node * HID + lane] = __float2half_rn(acc);
    }
}

// ---------------------------------------------------------------------------
// Single-pass exclusive scan (decoupled lookback), 98 blocks.
__global__ void scan_kernel() {
    __shared__ int sh[SCAN_BLK];
    __shared__ int s_prefix;
    int tid = threadIdx.x;
    int b = blockIdx.x;
    int i = b * SCAN_BLK + tid;
    int v = (i < NUM_NODES) ? g_counts[i] : 0;
    sh[tid] = v;
    __syncthreads();
#pragma unroll
    for (int off = 1; off < SCAN_BLK; off <<= 1) {
        int t = (tid >= off) ? sh[tid - off] : 0;
        __syncthreads();
        sh[tid] += t;
        __syncthreads();
    }
    int incl = sh[tid];
    int agg = sh[SCAN_BLK - 1];

    if (tid == 0) {
        int st = ((b == 0) ? ST_INCL : ST_AGG) | agg;
        atomicExch(&g_tile_state[b], st);
        if (b == 0) s_prefix = 0;
    }

    if (b > 0 && tid < 32) {
        int running = 0;
        int idx = b - 1;
        while (true) {
            int look = idx - tid;
            int st;
            if (look >= 0) {
                do { st = atomicAdd(&g_tile_state[look], 0); } while (st == 0);
            } else {
                st = ST_INCL;
            }
            int status = st & ~ST_VAL;
            int val    = st & ST_VAL;
            unsigned mask = __ballot_sync(0xffffffffu, status == ST_INCL);
            if (mask) {
                int first = __ffs(mask) - 1;
                int contrib = (tid <= first) ? val : 0;
#pragma unroll
                for (int o = 16; o > 0; o >>= 1)
                    contrib += __shfl_xor_sync(0xffffffffu, contrib, o);
                running += contrib;
                break;
            } else {
                int contrib = val;
#pragma unroll
                for (int o = 16; o > 0; o >>= 1)
                    contrib += __shfl_xor_sync(0xffffffffu, contrib, o);
                running += contrib;
                idx -= 32;
            }
        }
        if (tid == 0) {
            atomicExch(&g_tile_state[b], ST_INCL | (running + agg));
            s_prefix = running;
        }
    }
    __syncthreads();

    int prefix = s_prefix;
    if (i < NUM_NODES) {
        int excl = prefix + incl - v;
        g_row_ptr[i] = excl;
        g_counts[i]  = excl;          // cursor for permute
    }
    if (b == NB - 1 && tid == 0) g_row_ptr[NUM_NODES] = N_EDGES;
}

// ---------------------------------------------------------------------------
// CSR permute: 4 edges/thread; val stored as duplicated half2 for HFMA2.
__global__ void permute_kernel(const int* __restrict__ rows,
                               const int* __restrict__ cols,
                               const float* __restrict__ vals) {
    int t = blockIdx.x * blockDim.x + threadIdx.x;
    int e4 = t * 4;
    if (e4 + 3 < N_EDGES) {
        int4   r4 = *(const int4*)(rows + e4);
        int4   c4 = *(const int4*)(cols + e4);
        float4 v4 = *(const float4*)(vals + e4);
        int p0 = atomicAdd(&g_counts[r4.x], 1);
        int p1 = atomicAdd(&g_counts[r4.y], 1);
        int p2 = atomicAdd(&g_counts[r4.z], 1);
        int p3 = atomicAdd(&g_counts[r4.w], 1);
        __half2 h0 = __float2half2_rn(v4.x);
        __half2 h1 = __float2half2_rn(v4.y);
        __half2 h2 = __float2half2_rn(v4.z);
        __half2 h3 = __float2half2_rn(v4.w);
        g_epk[p0] = make_int2(c4.x, *(const int*)&h0);
        g_epk[p1] = make_int2(c4.y, *(const int*)&h1);
        g_epk[p2] = make_int2(c4.z, *(const int*)&h2);
        g_epk[p3] = make_int2(c4.w, *(const int*)&h3);
    } else {
        for (int e = e4; e < N_EDGES; e++) {
            int pos = atomicAdd(&g_counts[rows[e]], 1);
            __half2 hv = __float2half2_rn(vals[e]);
            g_epk[pos] = make_int2(cols[e], *(const int*)&hv);
        }
    }
}

// ---------------------------------------------------------------------------
// SpMM layer 1, balanced quads + chunked HFMA2: accumulate <=8 edges in
// half2 (4 HFMA2/edge, no converts), flush into fp32 each chunk.
__global__ void __launch_bounds__(256, 8) spmm1_kernel() {
    int lane = threadIdx.x & 31;
    int f = lane & 3;
    int quad = (blockIdx.x * (blockDim.x >> 5) + (threadIdx.x >> 5)) * 8 + (lane >> 2);
    int r0 = quad * 2;
    if (r0 >= NUM_NODES) return;
    const uint4* tbl = (const uint4*)g_h1h;

    int jb0 = __ldg(&g_row_ptr[r0]);
    int mid = __ldg(&g_row_ptr[r0 + 1]);
    int je1 = __ldg(&g_row_ptr[r0 + 2]);

#pragma unroll
    for (int rr = 0; rr < 2; rr++) {
        int jb = rr ? mid : jb0;
        int je = rr ? je1 : mid;
        float acc[8];
#pragma unroll
        for (int i = 0; i < 8; i++) acc[i] = 0.f;

        for (int jc = jb; jc < je; jc += 8) {
            __half2 ha0 = __float2half2_rn(0.f), ha1 = ha0, ha2 = ha0, ha3 = ha0;
            int jend = jc + 8 < je ? jc + 8 : je;
#pragma unroll 4
            for (int j = jc; j < jend; j++) {
                int2 cv = __ldg(&g_epk[j]);          // uniform within quad
                __half2 vh = *(const __half2*)&cv.y;
                uint4 hq = __ldg(&tbl[(size_t)cv.x * 4 + f]);
                const __half2* hp = (const __half2*)&hq;
                ha0 = __hfma2(vh, hp[0], ha0);
                ha1 = __hfma2(vh, hp[1], ha1);
                ha2 = __hfma2(vh, hp[2], ha2);
                ha3 = __hfma2(vh, hp[3], ha3);
            }
            float2 f0 = __half22float2(ha0);
            float2 f1 = __half22float2(ha1);
            float2 f2 = __half22float2(ha2);
            float2 f3 = __half22float2(ha3);
            acc[0] += f0.x; acc[1] += f0.y;
            acc[2] += f1.x; acc[3] += f1.y;
            acc[4] += f2.x; acc[5] += f2.y;
            acc[6] += f3.x; acc[7] += f3.y;
        }
        __half2 oh[4];
#pragma unroll
        for (int i = 0; i < 4; i++)
            oh[i] = __floats2half2_rn(fmaxf(acc[2 * i], 0.f),
                                      fmaxf(acc[2 * i + 1], 0.f));
        ((uint4*)g_yh)[(size_t)(r0 + rr) * 4 + f] = *(const uint4*)oh;
    }
}

// ---------------------------------------------------------------------------
// SpMM layer 2, balanced quads + chunked HFMA2; row-major agg + fp32 rowsum.
__global__ void __launch_bounds__(256, 8) spmm2_kernel() {
    int lane = threadIdx.x & 31;
    int f = lane & 3;
    int quad = (blockIdx.x * (blockDim.x >> 5) + (threadIdx.x >> 5)) * 8 + (lane >> 2);
    int r0 = quad * 2;
    if (r0 >= NUM_NODES) return;
    const uint4* tbl = (const uint4*)g_yh;

    int jb0 = __ldg(&g_row_ptr[r0]);
    int mid = __ldg(&g_row_ptr[r0 + 1]);
    int je1 = __ldg(&g_row_ptr[r0 + 2]);

#pragma unroll
    for (int rr = 0; rr < 2; rr++) {
        int jb = rr ? mid : jb0;
        int je = rr ? je1 : mid;
        int r = r0 + rr;
        float acc[8];
#pragma unroll
        for (int i = 0; i < 8; i++) acc[i] = 0.f;
        float s = 0.f;

        for (int jc = jb; jc < je; jc += 8) {
            __half2 ha0 = __float2half2_rn(0.f), ha1 = ha0, ha2 = ha0, ha3 = ha0;
            int jend = jc + 8 < je ? jc + 8 : je;
#pragma unroll 4
            for (int j = jc; j < jend; j++) {
                int2 cv = __ldg(&g_epk[j]);
                __half2 vh = *(const __half2*)&cv.y;
                uint4 hq = __ldg(&tbl[(size_t)cv.x * 4 + f]);
                const __half2* hp = (const __half2*)&hq;
                ha0 = __hfma2(vh, hp[0], ha0);
                ha1 = __hfma2(vh, hp[1], ha1);
                ha2 = __hfma2(vh, hp[2], ha2);
                ha3 = __hfma2(vh, hp[3], ha3);
                s += __low2float(vh);
            }
            float2 f0 = __half22float2(ha0);
            float2 f1 = __half22float2(ha1);
            float2 f2 = __half22float2(ha2);
            float2 f3 = __half22float2(ha3);
            acc[0] += f0.x; acc[1] += f0.y;
            acc[2] += f1.x; acc[3] += f1.y;
            acc[4] += f2.x; acc[5] += f2.y;
            acc[6] += f3.x; acc[7] += f3.y;
        }
        // coalesced: lane f writes float4 slots 2f, 2f+1 of the 128B row
        float4* ap = (float4*)(g_agg + (size_t)r * HID);
        ap[2 * f]     = make_float4(acc[0], acc[1], acc[2], acc[3]);
        ap[2 * f + 1] = make_float4(acc[4], acc[5], acc[6], acc[7]);
        if (f == 0) g_s[r] = s;
    }
}

// ---------------------------------------------------------------------------
// lin2out: out[n][o] = relu( sum_k agg[n][k]*W2[o][k] + s[n]*b2[o] ).
__global__ void lin2out_kernel(const float* __restrict__ W2,
                               const float* __restrict__ b2,
                               float* __restrict__ out_h2) {
    __shared__ float sW2[HID][EMB + 1];   // sW2[k][o] = W2[o][k]
    int tid = threadIdx.x;
    for (int i = tid; i < EMB * HID; i += blockDim.x) {
        int o = i >> 5, k = i & 31;
        sW2[k][o] = W2[i];
    }
    __syncthreads();

    int lane = tid & 31;
    float w0[HID], w1[HID];
#pragma unroll
    for (int k = 0; k < HID; k++) {
        w0[k] = sW2[k][lane];
        w1[k] = sW2[k][lane + 32];
    }
    float b0 = __ldg(&b2[lane]);
    float b1 = __ldg(&b2[lane + 32]);

    int warp = blockIdx.x * (blockDim.x >> 5) + (tid >> 5);
    int n0 = warp * 32;

    for (int n = n0; n < n0 + 32 && n < NUM_NODES; n++) {
        const float4* ap = (const float4*)(g_agg + (size_t)n * HID);
        float s = __ldg(&g_s[n]);
        float a0 = s * b0, a1 = s * b1;
#pragma unroll
        for (int c = 0; c < 8; c++) {
            float4 x = __ldg(&ap[c]);     // warp-uniform broadcast
            int k = c * 4;
            a0 += x.x * w0[k] + x.y * w0[k + 1] + x.z * w0[k + 2] + x.w * w0[k + 3];
            a1 += x.x * w1[k] + x.y * w1[k + 1] + x.z * w1[k + 2] + x.w * w1[k + 3];
        }
        out_h2[(size_t)n * EMB + lane]      = fmaxf(a0, 0.f);
        out_h2[(size_t)n * EMB + lane + 32] = fmaxf(a1, 0.f);
    }
}

// ---------------------------------------------------------------------------
// prediction MLP (smem-transposed weights) + state cleanup.
__global__ void predict_kernel(const int* __restrict__ uid,
                               const int* __restrict__ iid,
                               const float* __restrict__ h2,
                               const float* __restrict__ p1w,
                               const float* __restrict__ p1b,
                               const float* __restrict__ p2w,
                               const float* __restrict__ p2b,
                               float* __restrict__ scores) {
    int gt = blockIdx.x * blockDim.x + threadIdx.x;
    int nthr = gridDim.x * blockDim.x;
    for (int i = gt; i < NUM_NODES; i += nthr) g_counts[i] = 0;
    if (gt < NB) g_tile_state[gt] = 0;

    __shared__ float sP[2 * EMB][HID + 1];
    int tid = threadIdx.x;
    for (int i = tid; i < HID * 2 * EMB; i += blockDim.x) {
        int j = i >> 7, k = i & 127;
        sP[k][j] = p1w[i];
    }
    __syncthreads();

    int lane = tid & 31;
    float w[2 * EMB];
#pragma unroll
    for (int k = 0; k < 2 * EMB; k++) w[k] = sP[k][lane];
    float bias = __ldg(&p1b[lane]);
    float w2   = __ldg(&p2w[lane]);
    float b2v  = __ldg(&p2b[0]);

    int warp   = blockIdx.x * (blockDim.x >> 5) + (tid >> 5);
    int nwarps = gridDim.x * (blockDim.x >> 5);

    for (int s = warp; s < BATCH; s += nwarps) {
        int u  = __ldg(&uid[s]);
        int it = __ldg(&iid[s]);
        const float* bu = h2 + (size_t)u * EMB;
        const float* bi = h2 + (size_t)(NUM_USERS + it) * EMB;
        float x0 = bu[lane], x1 = bu[lane + 32];
        float x2 = bi[lane], x3 = bi[lane + 32];
        float acc = bias;
#pragma unroll
        for (int k = 0; k < 32; k++) {
            acc += __shfl_sync(0xffffffffu, x0, k) * w[k];
            acc += __shfl_sync(0xffffffffu, x1, k) * w[k + 32];
            acc += __shfl_sync(0xffffffffu, x2, k) * w[k + 64];
            acc += __shfl_sync(0xffffffffu, x3, k) * w[k + 96];
        }
        float z = fmaxf(acc, 0.f) * w2;
#pragma unroll
        for (int o = 16; o > 0; o >>= 1)
            z += __shfl_xor_sync(0xffffffffu, z, o);
        if (lane == 0)
            scores[s] = 1.f / (1.f + expf(-(z + b2v)));
    }
}

// ---------------------------------------------------------------------------
extern "C" void kernel_launch(void* const* d_in, const int* in_sizes, int n_in,
                              void* d_out, int out_size) {
    const int*   user_ids = (const int*)d_in[0];
    const int*   item_ids = (const int*)d_in[1];
    const int*   adj_rows = (const int*)d_in[2];
    const int*   adj_cols = (const int*)d_in[3];
    const float* adj_vals = (const float*)d_in[4];
    const float* uemb     = (const float*)d_in[5];
    const float* iemb     = (const float*)d_in[6];
    const float* gc1w     = (const float*)d_in[7];
    const float* gc1b     = (const float*)d_in[8];
    const float* gc2w     = (const float*)d_in[9];
    const float* gc2b     = (const float*)d_in[10];
    const float* p1w      = (const float*)d_in[11];
    const float* p1b      = (const float*)d_in[12];
    const float* p2w      = (const float*)d_in[13];
    const float* p2b      = (const float*)d_in[14];

    float* out    = (float*)d_out;
    float* out_h2 = out + BATCH;   // [NUM_NODES*EMB] = concat(user_emb, item_emb)

    const int TB = 256;
    const int E4 = (N_EDGES / 4 + TB - 1) / TB;
    const int SPMM_BLOCKS = (NUM_NODES / 2 + 63) / 64;            // 782
    const int L2O_BLOCKS  = (NUM_NODES + 32 * 8 - 1) / (32 * 8);  // 391

    // 1: fused lin1 (fp16 table, smem-transposed W1) + degree histogram
    lin1_hist_kernel<<<592, TB>>>(uemb, iemb, gc1w, gc1b, adj_rows);
    // 2: single-pass lookback scan -> row_ptr + cursor
    scan_kernel<<<NB, SCAN_BLK>>>();
    // 3: CSR permute (val pre-converted to half2)
    permute_kernel<<<E4, TB>>>(adj_rows, adj_cols, adj_vals);
    // 4: layer-1 aggregate + ReLU (balanced quads, chunked HFMA2)
    spmm1_kernel<<<SPMM_BLOCKS, TB>>>();
    // 5: layer-2 aggregate -> row-major agg + rowsum (chunked HFMA2)
    spmm2_kernel<<<SPMM_BLOCKS, TB>>>();
    // 6: dense lin2 + bias + ReLU -> d_out embeddings
    lin2out_kernel<<<L2O_BLOCKS, TB>>>(gc2w, gc2b, out_h2);
    // 7: prediction head (smem-transposed p1w) + state cleanup
    predict_kernel<<<148, TB>>>(user_ids, item_ids, out_h2,
                                p1w, p1b, p2w, p2b, out);
}

// round 17
// speedup vs baseline: 1.0113x; 1.0113x over previous
#include <cuda_runtime.h>
#include <math.h>

#define NUM_USERS 60000
#define NUM_ITEMS 40000
#define NUM_NODES 100000
#define EMB 64
#define HID 32
#define N_EDGES 1600000
#define BATCH 16384

#define SCAN_BLK 1024
#define NB ((NUM_NODES + SCAN_BLK - 1) / SCAN_BLK)   // 98

#define ST_AGG  (1 << 30)
#define ST_INCL (2 << 30)
#define ST_VAL  0x3FFFFFFF

#define HIST_BLOCKS 148

// ---------------- device scratch (allocation-free rule) ----------------
__device__ __align__(16) float g_h1[NUM_NODES * HID];    // lin1 out, fp32 (128B/row)
__device__ __align__(16) float g_y[NUM_NODES * HID];     // relu(agg1), fp32 (128B/row)
__device__ __align__(16) float g_agg[NUM_NODES * HID];   // layer-2 agg, row-major [node][k]
__device__ float g_s[NUM_NODES];                         // per-row sum of vals
__device__ int   g_counts[NUM_NODES];                    // degree hist / cursor (zeroed by predict tail)
__device__ int   g_row_ptr[NUM_NODES + 1];
__device__ int   g_tile_state[NB];                       // lookback states (zeroed by predict tail)
__device__ __align__(8) int2 g_epk[N_EDGES];             // (col, val-bits fp32), CSR order

// ---------------------------------------------------------------------------
// Fused lin1 + degree histogram. Blocks [0,HIST_BLOCKS) histogram; rest lin1.
__global__ void lin1_hist_kernel(const float* __restrict__ uemb,
                                 const float* __restrict__ iemb,
                                 const float* __restrict__ W,
                                 const float* __restrict__ b,
                                 const int* __restrict__ rows) {
    int lane = threadIdx.x & 31;

    if (blockIdx.x < HIST_BLOCKS) {
        int t = blockIdx.x * blockDim.x + threadIdx.x;
        int nthr = HIST_BLOCKS * blockDim.x;
        for (int e4 = t * 4; e4 < N_EDGES; e4 += nthr * 4) {
            int4 r4 = *(const int4*)(rows + e4);      // N_EDGES % 4 == 0
            atomicAdd(&g_counts[r4.x], 1);
            atomicAdd(&g_counts[r4.y], 1);
            atomicAdd(&g_counts[r4.z], 1);
            atomicAdd(&g_counts[r4.w], 1);
        }
        return;
    }

    __shared__ float sW[EMB][HID + 1];   // sW[k][j] = W1[j][k]
    int tid = threadIdx.x;
    for (int i = tid; i < HID * EMB; i += blockDim.x) {
        int j = i >> 6, k = i & 63;      // W row-major [j][k], coalesced read
        sW[k][j] = W[i];
    }
    __syncthreads();

    float w[EMB];
#pragma unroll
    for (int k = 0; k < EMB; k++) w[k] = sW[k][lane];   // conflict-free
    float bias = __ldg(&b[lane]);

    int wl = (blockIdx.x - HIST_BLOCKS) * (blockDim.x >> 5) + (tid >> 5);
    int nl = (gridDim.x - HIST_BLOCKS) * (blockDim.x >> 5);

    for (int node = wl; node < NUM_NODES; node += nl) {
        const float* feat = (node < NUM_USERS)
            ? uemb + (size_t)node * EMB
            : iemb + (size_t)(node - NUM_USERS) * EMB;
        float x0 = __ldg(&feat[lane]);
        float x1 = __ldg(&feat[lane + 32]);
        float acc = bias;
#pragma unroll
        for (int k = 0; k < 32; k++) {
            acc += __shfl_sync(0xffffffffu, x0, k) * w[k];
            acc += __shfl_sync(0xffffffffu, x1, k) * w[k + 32];
        }
        g_h1[(size_t)node * HID + lane] = acc;
    }
}

// ---------------------------------------------------------------------------
// Single-pass exclusive scan (decoupled lookback), 98 blocks.
__global__ void scan_kernel() {
    __shared__ int sh[SCAN_BLK];
    __shared__ int s_prefix;
    int tid = threadIdx.x;
    int b = blockIdx.x;
    int i = b * SCAN_BLK + tid;
    int v = (i < NUM_NODES) ? g_counts[i] : 0;
    sh[tid] = v;
    __syncthreads();
#pragma unroll
    for (int off = 1; off < SCAN_BLK; off <<= 1) {
        int t = (tid >= off) ? sh[tid - off] : 0;
        __syncthreads();
        sh[tid] += t;
        __syncthreads();
    }
    int incl = sh[tid];
    int agg = sh[SCAN_BLK - 1];

    if (tid == 0) {
        int st = ((b == 0) ? ST_INCL : ST_AGG) | agg;
        atomicExch(&g_tile_state[b], st);
        if (b == 0) s_prefix = 0;
    }

    if (b > 0 && tid < 32) {
        int running = 0;
        int idx = b - 1;
        while (true) {
            int look = idx - tid;
            int st;
            if (look >= 0) {
                do { st = atomicAdd(&g_tile_state[look], 0); } while (st == 0);
            } else {
                st = ST_INCL;
            }
            int status = st & ~ST_VAL;
            int val    = st & ST_VAL;
            unsigned mask = __ballot_sync(0xffffffffu, status == ST_INCL);
            if (mask) {
                int first = __ffs(mask) - 1;
                int contrib = (tid <= first) ? val : 0;
#pragma unroll
                for (int o = 16; o > 0; o >>= 1)
                    contrib += __shfl_xor_sync(0xffffffffu, contrib, o);
                running += contrib;
                break;
            } else {
                int contrib = val;
#pragma unroll
                for (int o = 16; o > 0; o >>= 1)
                    contrib += __shfl_xor_sync(0xffffffffu, contrib, o);
                running += contrib;
                idx -= 32;
            }
        }
        if (tid == 0) {
            atomicExch(&g_tile_state[b], ST_INCL | (running + agg));
            s_prefix = running;
        }
    }
    __syncthreads();

    int prefix = s_prefix;
    if (i < NUM_NODES) {
        int excl = prefix + incl - v;
        g_row_ptr[i] = excl;
        g_counts[i]  = excl;          // cursor for permute
    }
    if (b == NB - 1 && tid == 0) g_row_ptr[NUM_NODES] = N_EDGES;
}

// ---------------------------------------------------------------------------
// CSR permute: 4 edges/thread (fp32 val bits)
__global__ void permute_kernel(const int* __restrict__ rows,
                               const int* __restrict__ cols,
                               const float* __restrict__ vals) {
    int t = blockIdx.x * blockDim.x + threadIdx.x;
    int e4 = t * 4;
    if (e4 + 3 < N_EDGES) {
        int4   r4 = *(const int4*)(rows + e4);
        int4   c4 = *(const int4*)(cols + e4);
        float4 v4 = *(const float4*)(vals + e4);
        int p0 = atomicAdd(&g_counts[r4.x], 1);
        int p1 = atomicAdd(&g_counts[r4.y], 1);
        int p2 = atomicAdd(&g_counts[r4.z], 1);
        int p3 = atomicAdd(&g_counts[r4.w], 1);
        g_epk[p0] = make_int2(c4.x, __float_as_int(v4.x));
        g_epk[p1] = make_int2(c4.y, __float_as_int(v4.y));
        g_epk[p2] = make_int2(c4.z, __float_as_int(v4.z));
        g_epk[p3] = make_int2(c4.w, __float_as_int(v4.w));
    } else {
        for (int e = e4; e < N_EDGES; e++) {
            int pos = atomicAdd(&g_counts[rows[e]], 1);
            g_epk[pos] = make_int2(cols[e], __float_as_int(vals[e]));
        }
    }
}

// ---------------------------------------------------------------------------
// SpMM layer 1, balanced quads, fp32 tables: quad q handles rows {2q, 2q+1};
// lane f=lane&3 owns float4 slots {2f, 2f+1} (32B of the 128B row).
// Per edge: 1 LDG.64 + 2 LDG.128 + 8 FFMA, all chains independent.
__global__ void __launch_bounds__(256, 8) spmm1_kernel() {
    int lane = threadIdx.x & 31;
    int f = lane & 3;
    int quad = (blockIdx.x * (blockDim.x >> 5) + (threadIdx.x >> 5)) * 8 + (lane >> 2);
    int r0 = quad * 2;
    if (r0 >= NUM_NODES) return;
    const float4* tbl = (const float4*)g_h1;

    int jb0 = __ldg(&g_row_ptr[r0]);
    int mid = __ldg(&g_row_ptr[r0 + 1]);
    int je1 = __ldg(&g_row_ptr[r0 + 2]);

#pragma unroll
    for (int rr = 0; rr < 2; rr++) {
        int jb = rr ? mid : jb0;
        int je = rr ? je1 : mid;
        float4 a0 = make_float4(0.f, 0.f, 0.f, 0.f);
        float4 a1 = make_float4(0.f, 0.f, 0.f, 0.f);
#pragma unroll 4
        for (int j = jb; j < je; j++) {
            int2 cv = __ldg(&g_epk[j]);              // uniform within quad
            float v = __int_as_float(cv.y);
            float4 x0 = __ldg(&tbl[(size_t)cv.x * 8 + 2 * f]);
            float4 x1 = __ldg(&tbl[(size_t)cv.x * 8 + 2 * f + 1]);
            a0.x += v * x0.x; a0.y += v * x0.y; a0.z += v * x0.z; a0.w += v * x0.w;
            a1.x += v * x1.x; a1.y += v * x1.y; a1.z += v * x1.z; a1.w += v * x1.w;
        }
        float4* op = (float4*)(g_y + (size_t)(r0 + rr) * HID);
        op[2 * f]     = make_float4(fmaxf(a0.x, 0.f), fmaxf(a0.y, 0.f),
                                    fmaxf(a0.z, 0.f), fmaxf(a0.w, 0.f));
        op[2 * f + 1] = make_float4(fmaxf(a1.x, 0.f), fmaxf(a1.y, 0.f),
                                    fmaxf(a1.z, 0.f), fmaxf(a1.w, 0.f));
    }
}

// ---------------------------------------------------------------------------
// SpMM layer 2, balanced quads, fp32 tables: row-major agg + rowsum.
__global__ void __launch_bounds__(256, 8) spmm2_kernel() {
    int lane = threadIdx.x & 31;
    int f = lane & 3;
    int quad = (blockIdx.x * (blockDim.x >> 5) + (threadIdx.x >> 5)) * 8 + (lane >> 2);
    int r0 = quad * 2;
    if (r0 >= NUM_NODES) return;
    const float4* tbl = (const float4*)g_y;

    int jb0 = __ldg(&g_row_ptr[r0]);
    int mid = __ldg(&g_row_ptr[r0 + 1]);
    int je1 = __ldg(&g_row_ptr[r0 + 2]);

#pragma unroll
    for (int rr = 0; rr < 2; rr++) {
        int jb = rr ? mid : jb0;
        int je = rr ? je1 : mid;
        int r = r0 + rr;
        float4 a0 = make_float4(0.f, 0.f, 0.f, 0.f);
        float4 a1 = make_float4(0.f, 0.f, 0.f, 0.f);
        float s = 0.f;
#pragma unroll 4
        for (int j = jb; j < je; j++) {
            int2 cv = __ldg(&g_epk[j]);
            float v = __int_as_float(cv.y);
            float4 x0 = __ldg(&tbl[(size_t)cv.x * 8 + 2 * f]);
            float4 x1 = __ldg(&tbl[(size_t)cv.x * 8 + 2 * f + 1]);
            a0.x += v * x0.x; a0.y += v * x0.y; a0.z += v * x0.z; a0.w += v * x0.w;
            a1.x += v * x1.x; a1.y += v * x1.y; a1.z += v * x1.z; a1.w += v * x1.w;
            s += v;
        }
        float4* ap = (float4*)(g_agg + (size_t)r * HID);
        ap[2 * f]     = a0;
        ap[2 * f + 1] = a1;
        if (f == 0) g_s[r] = s;
    }
}

// ---------------------------------------------------------------------------
// lin2out: out[n][o] = relu( sum_k agg[n][k]*W2[o][k] + s[n]*b2[o] ).
__global__ void lin2out_kernel(const float* __restrict__ W2,
                               const float* __restrict__ b2,
                               float* __restrict__ out_h2) {
    __shared__ float sW2[HID][EMB + 1];   // sW2[k][o] = W2[o][k]
    int tid = threadIdx.x;
    for (int i = tid; i < EMB * HID; i += blockDim.x) {
        int o = i >> 5, k = i & 31;
        sW2[k][o] = W2[i];
    }
    __syncthreads();

    int lane = tid & 31;
    float w0[HID], w1[HID];
#pragma unroll
    for (int k = 0; k < HID; k++) {
        w0[k] = sW2[k][lane];
        w1[k] = sW2[k][lane + 32];
    }
    float b0 = __ldg(&b2[lane]);
    float b1 = __ldg(&b2[lane + 32]);

    int warp = blockIdx.x * (blockDim.x >> 5) + (tid >> 5);
    int n0 = warp * 32;

    for (int n = n0; n < n0 + 32 && n < NUM_NODES; n++) {
        const float4* ap = (const float4*)(g_agg + (size_t)n * HID);
        float s = __ldg(&g_s[n]);
        float a0 = s * b0, a1 = s * b1;
#pragma unroll
        for (int c = 0; c < 8; c++) {
            float4 x = __ldg(&ap[c]);     // warp-uniform broadcast
            int k = c * 4;
            a0 += x.x * w0[k] + x.y * w0[k + 1] + x.z * w0[k + 2] + x.w * w0[k + 3];
            a1 += x.x * w1[k] + x.y * w1[k + 1] + x.z * w1[k + 2] + x.w * w1[k + 3];
        }
        out_h2[(size_t)n * EMB + lane]      = fmaxf(a0, 0.f);
        out_h2[(size_t)n * EMB + lane + 32] = fmaxf(a1, 0.f);
    }
}

// ---------------------------------------------------------------------------
// prediction MLP (smem-transposed weights) + state cleanup.
__global__ void predict_kernel(const int* __restrict__ uid,
                               const int* __restrict__ iid,
                               const float* __restrict__ h2,
                               const float* __restrict__ p1w,
                               const float* __restrict__ p1b,
                               const float* __restrict__ p2w,
                               const float* __restrict__ p2b,
                               float* __restrict__ scores) {
    int gt = blockIdx.x * blockDim.x + threadIdx.x;
    int nthr = gridDim.x * blockDim.x;
    for (int i = gt; i < NUM_NODES; i += nthr) g_counts[i] = 0;
    if (gt < NB) g_tile_state[gt] = 0;

    __shared__ float sP[2 * EMB][HID + 1];
    int tid = threadIdx.x;
    for (int i = tid; i < HID * 2 * EMB; i += blockDim.x) {
        int j = i >> 7, k = i & 127;
        sP[k][j] = p1w[i];
    }
    __syncthreads();

    int lane = tid & 31;
    float w[2 * EMB];
#pragma unroll
    for (int k = 0; k < 2 * EMB; k++) w[k] = sP[k][lane];
    float bias = __ldg(&p1b[lane]);
    float w2   = __ldg(&p2w[lane]);
    float b2v  = __ldg(&p2b[0]);

    int warp   = blockIdx.x * (blockDim.x >> 5) + (tid >> 5);
    int nwarps = gridDim.x * (blockDim.x >> 5);

    for (int s = warp; s < BATCH; s += nwarps) {
        int u  = __ldg(&uid[s]);
        int it = __ldg(&iid[s]);
        const float* bu = h2 + (size_t)u * EMB;
        const float* bi = h2 + (size_t)(NUM_USERS + it) * EMB;
        float x0 = bu[lane], x1 = bu[lane + 32];
        float x2 = bi[lane], x3 = bi[lane + 32];
        float acc = bias;
#pragma unroll
        for (int k = 0; k < 32; k++) {
            acc += __shfl_sync(0xffffffffu, x0, k) * w[k];
            acc += __shfl_sync(0xffffffffu, x1, k) * w[k + 32];
            acc += __shfl_sync(0xffffffffu, x2, k) * w[k + 64];
            acc += __shfl_sync(0xffffffffu, x3, k) * w[k + 96];
        }
        float z = fmaxf(acc, 0.f) * w2;
#pragma unroll
        for (int o = 16; o > 0; o >>= 1)
            z += __shfl_xor_sync(0xffffffffu, z, o);
        if (lane == 0)
            scores[s] = 1.f / (1.f + expf(-(z + b2v)));
    }
}

// ---------------------------------------------------------------------------
extern "C" void kernel_launch(void* const* d_in, const int* in_sizes, int n_in,
                              void* d_out, int out_size) {
    const int*   user_ids = (const int*)d_in[0];
    const int*   item_ids = (const int*)d_in[1];
    const int*   adj_rows = (const int*)d_in[2];
    const int*   adj_cols = (const int*)d_in[3];
    const float* adj_vals = (const float*)d_in[4];
    const float* uemb     = (const float*)d_in[5];
    const float* iemb     = (const float*)d_in[6];
    const float* gc1w     = (const float*)d_in[7];
    const float* gc1b     = (const float*)d_in[8];
    const float* gc2w     = (const float*)d_in[9];
    const float* gc2b     = (const float*)d_in[10];
    const float* p1w      = (const float*)d_in[11];
    const float* p1b      = (const float*)d_in[12];
    const float* p2w      = (const float*)d_in[13];
    const float* p2b      = (const float*)d_in[14];

    float* out    = (float*)d_out;
    float* out_h2 = out + BATCH;   // [NUM_NODES*EMB] = concat(user_emb, item_emb)

    const int TB = 256;
    const int E4 = (N_EDGES / 4 + TB - 1) / TB;
    const int SPMM_BLOCKS = (NUM_NODES / 2 + 63) / 64;            // 782
    const int L2O_BLOCKS  = (NUM_NODES + 32 * 8 - 1) / (32 * 8);  // 391

    // 1: fused lin1 (fp32 table, smem-transposed W1) + degree histogram
    lin1_hist_kernel<<<592, TB>>>(uemb, iemb, gc1w, gc1b, adj_rows);
    // 2: single-pass lookback scan -> row_ptr + cursor
    scan_kernel<<<NB, SCAN_BLK>>>();
    // 3: CSR permute
    permute_kernel<<<E4, TB>>>(adj_rows, adj_cols, adj_vals);
    // 4: layer-1 aggregate + ReLU (balanced quads, fp32, no converts)
    spmm1_kernel<<<SPMM_BLOCKS, TB>>>();
    // 5: layer-2 aggregate -> row-major agg + rowsum (fp32, no converts)
    spmm2_kernel<<<SPMM_BLOCKS, TB>>>();
    // 6: dense lin2 + bias + ReLU -> d_out embeddings
    lin2out_kernel<<<L2O_BLOCKS, TB>>>(gc2w, gc2b, out_h2);
    // 7: prediction head (smem-transposed p1w) + state cleanup
    predict_kernel<<<148, TB>>>(user_ids, item_ids, out_h2,
                                p1w, p1b, p2w, p2b, out);
}